// round 1
// baseline (speedup 1.0000x reference)
#include <cuda_runtime.h>
#include <cstddef>

// ---------------------------------------------------------------------------
// Problem constants
// ---------------------------------------------------------------------------
#define DIMC     512
#define NHEADS   16
#define HD       32
#define NTOK     64          // window size 8x8
#define NWIN     1024
#define MTOT     (NWIN * NTOK)      // 65536 rows
#define QKV_COLS (3 * DIMC)         // 1536

// Scratch (device globals: allocation rules forbid cudaMalloc)
__device__ float g_qkv[(size_t)MTOT * QKV_COLS];  // 402 MB
__device__ float g_att[(size_t)MTOT * DIMC];      // 134 MB

// ---------------------------------------------------------------------------
// SGEMM (NT): C[M,N] = A[M,K] * B[N,K]^T + bias[N]
// 128x128 CTA tile, BK=8, 256 threads, 8x8 per-thread micro-tile,
// double-buffered shared memory, float4 global loads / smem reads.
// Requires M%128==0, N%128==0, K%8==0 (true for both GEMMs here).
// ---------------------------------------------------------------------------
__global__ __launch_bounds__(256) void sgemm_nt_bias(
    const float* __restrict__ A, const float* __restrict__ Bm,
    const float* __restrict__ bias, float* __restrict__ C,
    int M, int N, int K)
{
    constexpr int BM = 128, BN = 128, BK = 8;
    __shared__ float As[2][BK][BM];
    __shared__ float Bs[2][BK][BN];

    const int tid = threadIdx.x;
    const int bm  = blockIdx.y * BM;
    const int bn  = blockIdx.x * BN;

    // loading map: each thread loads one float4 of A and one of B per K-tile
    const int lr = tid >> 1;            // 0..127 (row within tile)
    const int lc = (tid & 1) << 2;      // 0 or 4 (k-offset)

    // compute map: 16x16 thread grid, 8x8 outputs each
    const int ty = tid >> 4;            // 0..15
    const int tx = tid & 15;            // 0..15

    const float* Aptr = A  + (size_t)(bm + lr) * K + lc;
    const float* Bptr = Bm + (size_t)(bn + lr) * K + lc;

    // preload tile 0
    float4 a4 = *(const float4*)Aptr;
    float4 b4 = *(const float4*)Bptr;
    As[0][lc + 0][lr] = a4.x; As[0][lc + 1][lr] = a4.y;
    As[0][lc + 2][lr] = a4.z; As[0][lc + 3][lr] = a4.w;
    Bs[0][lc + 0][lr] = b4.x; Bs[0][lc + 1][lr] = b4.y;
    Bs[0][lc + 2][lr] = b4.z; Bs[0][lc + 3][lr] = b4.w;
    __syncthreads();

    float acc[8][8] = {};
    const int nt = K / BK;
    int buf = 0;

    for (int t = 0; t < nt; ++t) {
        if (t + 1 < nt) {   // stage next K-tile into registers
            a4 = *(const float4*)(Aptr + (t + 1) * BK);
            b4 = *(const float4*)(Bptr + (t + 1) * BK);
        }
        #pragma unroll
        for (int kk = 0; kk < BK; ++kk) {
            const float4* ap = (const float4*)&As[buf][kk][ty * 8];
            const float4* bp = (const float4*)&Bs[buf][kk][tx * 8];
            float4 af0 = ap[0], af1 = ap[1];
            float4 bf0 = bp[0], bf1 = bp[1];
            float af[8] = {af0.x, af0.y, af0.z, af0.w, af1.x, af1.y, af1.z, af1.w};
            float bf[8] = {bf0.x, bf0.y, bf0.z, bf0.w, bf1.x, bf1.y, bf1.z, bf1.w};
            #pragma unroll
            for (int m = 0; m < 8; ++m)
                #pragma unroll
                for (int n = 0; n < 8; ++n)
                    acc[m][n] += af[m] * bf[n];
        }
        if (t + 1 < nt) {
            const int nb = buf ^ 1;
            As[nb][lc + 0][lr] = a4.x; As[nb][lc + 1][lr] = a4.y;
            As[nb][lc + 2][lr] = a4.z; As[nb][lc + 3][lr] = a4.w;
            Bs[nb][lc + 0][lr] = b4.x; Bs[nb][lc + 1][lr] = b4.y;
            Bs[nb][lc + 2][lr] = b4.z; Bs[nb][lc + 3][lr] = b4.w;
        }
        __syncthreads();
        buf ^= 1;
    }

    // epilogue: add bias, float4 stores
    float bv[8];
    #pragma unroll
    for (int n = 0; n < 8; ++n) bv[n] = bias[bn + tx * 8 + n];

    #pragma unroll
    for (int m = 0; m < 8; ++m) {
        const int row = bm + ty * 8 + m;
        float* Crow = C + (size_t)row * N + bn + tx * 8;
        float4 o0 = make_float4(acc[m][0] + bv[0], acc[m][1] + bv[1],
                                acc[m][2] + bv[2], acc[m][3] + bv[3]);
        float4 o1 = make_float4(acc[m][4] + bv[4], acc[m][5] + bv[5],
                                acc[m][6] + bv[6], acc[m][7] + bv[7]);
        *(float4*)(Crow)     = o0;
        *(float4*)(Crow + 4) = o1;
    }
}

// ---------------------------------------------------------------------------
// Window attention: one CTA per (window b, head h). 256 threads.
// q,k,v [64,32] in padded smem (row stride 36 floats => 144B, 16B-aligned
// float4 access, conflict-free). Softmax over 64 cols per row with relative
// bias added pre-softmax and relative scale applied post-softmax.
// Thread map: 64 row-groups of 4 lanes; each lane owns 16 interleaved cols.
// ---------------------------------------------------------------------------
__global__ __launch_bounds__(256) void win_attn_kernel(
    const float* __restrict__ qkv, const float* __restrict__ table,
    const int* __restrict__ relidx, float* __restrict__ attout)
{
    const int blk = blockIdx.x;
    const int b   = blk >> 4;
    const int h   = blk & 15;
    const int tid = threadIdx.x;

    __shared__ float sq[64][36];
    __shared__ float sk[64][36];
    __shared__ float sv[64][36];
    __shared__ float sp[64][65];
    __shared__ float bias_h[225];
    __shared__ float scale_h[225];

    const size_t base = (size_t)b * NTOK * QKV_COLS + (size_t)h * HD;

    // load q,k,v tiles: 512 float4 per matrix, 2 per thread
    #pragma unroll
    for (int r = 0; r < 2; ++r) {
        const int idx = tid + 256 * r;        // 0..511
        const int row = idx >> 3;             // 0..63
        const int c4  = (idx & 7) * 4;        // 0,4,...,28
        const float* gp = qkv + base + (size_t)row * QKV_COLS + c4;
        float4 q4 = *(const float4*)(gp);
        float4 k4 = *(const float4*)(gp + DIMC);
        float4 v4 = *(const float4*)(gp + 2 * DIMC);
        sq[row][c4 + 0] = q4.x; sq[row][c4 + 1] = q4.y;
        sq[row][c4 + 2] = q4.z; sq[row][c4 + 3] = q4.w;
        sk[row][c4 + 0] = k4.x; sk[row][c4 + 1] = k4.y;
        sk[row][c4 + 2] = k4.z; sk[row][c4 + 3] = k4.w;
        sv[row][c4 + 0] = v4.x; sv[row][c4 + 1] = v4.y;
        sv[row][c4 + 2] = v4.z; sv[row][c4 + 3] = v4.w;
    }
    if (tid < 225) {
        bias_h[tid]  = table[tid * (2 * NHEADS) + h];
        scale_h[tid] = table[tid * (2 * NHEADS) + NHEADS + h];
    }
    __syncthreads();

    const int i = tid >> 2;      // attention row 0..63
    const int l = tid & 3;       // lane within 4-thread row group

    // q row in registers
    float4 qr[8];
    #pragma unroll
    for (int kk = 0; kk < 8; ++kk) qr[kk] = *(const float4*)&sq[i][kk * 4];

    const float scale = 0.17677669529663687f;  // 32^-0.5
    const int* ri = relidx + i * 64;

    float s[16];
    #pragma unroll
    for (int jj = 0; jj < 16; ++jj) {
        const int j = l + jj * 4;
        float acc = 0.f;
        #pragma unroll
        for (int kk = 0; kk < 8; ++kk) {
            const float4 kv = *(const float4*)&sk[j][kk * 4];
            acc += qr[kk].x * kv.x + qr[kk].y * kv.y
                 + qr[kk].z * kv.z + qr[kk].w * kv.w;
        }
        s[jj] = acc * scale + bias_h[ri[j]];
    }

    // row max over 64 (16 local + xor-shuffle across the 4-lane group)
    float mx = s[0];
    #pragma unroll
    for (int jj = 1; jj < 16; ++jj) mx = fmaxf(mx, s[jj]);
    mx = fmaxf(mx, __shfl_xor_sync(0xffffffffu, mx, 1, 4));
    mx = fmaxf(mx, __shfl_xor_sync(0xffffffffu, mx, 2, 4));

    float e[16], sum = 0.f;
    #pragma unroll
    for (int jj = 0; jj < 16; ++jj) { e[jj] = expf(s[jj] - mx); sum += e[jj]; }
    sum += __shfl_xor_sync(0xffffffffu, sum, 1, 4);
    sum += __shfl_xor_sync(0xffffffffu, sum, 2, 4);
    const float inv = 1.f / sum;

    #pragma unroll
    for (int jj = 0; jj < 16; ++jj) {
        const int j = l + jj * 4;
        sp[i][j] = e[jj] * inv * scale_h[ri[j]];
    }
    __syncwarp();   // row i written/read only within its own 4-lane group (same warp)

    // O[i, l*8 .. l*8+7] = sum_j P[i,j] * V[j, :]
    float o[8] = {0.f, 0.f, 0.f, 0.f, 0.f, 0.f, 0.f, 0.f};
    #pragma unroll
    for (int j = 0; j < 64; ++j) {
        const float p = sp[i][j];
        const float4 v0 = *(const float4*)&sv[j][l * 8];
        const float4 v1 = *(const float4*)&sv[j][l * 8 + 4];
        o[0] += p * v0.x; o[1] += p * v0.y; o[2] += p * v0.z; o[3] += p * v0.w;
        o[4] += p * v1.x; o[5] += p * v1.y; o[6] += p * v1.z; o[7] += p * v1.w;
    }

    float* op = attout + ((size_t)(b * NTOK + i)) * DIMC + h * HD + l * 8;
    *(float4*)(op)     = make_float4(o[0], o[1], o[2], o[3]);
    *(float4*)(op + 4) = make_float4(o[4], o[5], o[6], o[7]);
}

// ---------------------------------------------------------------------------
// Launch
// ---------------------------------------------------------------------------
extern "C" void kernel_launch(void* const* d_in, const int* in_sizes, int n_in,
                              void* d_out, int out_size)
{
    const float* x      = (const float*)d_in[0];
    const float* qkv_w  = (const float*)d_in[1];
    const float* qkv_b  = (const float*)d_in[2];
    const float* proj_w = (const float*)d_in[3];
    const float* proj_b = (const float*)d_in[4];
    const float* table  = (const float*)d_in[5];
    const int*   relidx = (const int*)d_in[6];
    float*       out    = (float*)d_out;

    float* qkvbuf = nullptr;
    float* attbuf = nullptr;
    cudaGetSymbolAddress((void**)&qkvbuf, g_qkv);
    cudaGetSymbolAddress((void**)&attbuf, g_att);

    // 1) QKV GEMM: [65536,512] x [1536,512]^T -> [65536,1536]
    sgemm_nt_bias<<<dim3(QKV_COLS / 128, MTOT / 128), 256>>>(
        x, qkv_w, qkv_b, qkvbuf, MTOT, QKV_COLS, DIMC);

    // 2) windowed attention: one CTA per (window, head)
    win_attn_kernel<<<NWIN * NHEADS, 256>>>(qkvbuf, table, relidx, attbuf);

    // 3) projection GEMM: [65536,512] x [512,512]^T -> out
    sgemm_nt_bias<<<dim3(DIMC / 128, MTOT / 128), 256>>>(
        attbuf, proj_w, proj_b, out, MTOT, DIMC, DIMC);
}

// round 2
// speedup vs baseline: 1.8614x; 1.8614x over previous
#include <cuda_runtime.h>
#include <cstdint>
#include <cstddef>

// ---------------------------------------------------------------------------
// Problem constants
// ---------------------------------------------------------------------------
#define DIMC     512
#define NHEADS   16
#define HD       32
#define NTOK     64          // window size 8x8
#define NWIN     1024
#define MTOT     (NWIN * NTOK)      // 65536 rows
#define QKV_COLS (3 * DIMC)         // 1536

// Scratch (device globals: allocation rules forbid cudaMalloc)
__device__ float g_qkv[(size_t)MTOT * QKV_COLS];  // 402 MB
__device__ float g_att[(size_t)MTOT * DIMC];      // 134 MB

// ---------------------------------------------------------------------------
// TF32 tensor-core GEMM (NT): C[M,N] = A[M,K] * B[N,K]^T + bias[N]
// CTA tile 128x128, BK=16, 256 threads (8 warps), warp tile 32x64,
// mma.sync.aligned.m16n8k8.row.col.f32.tf32.tf32.f32.
// A and B staged k-major in smem, stride 136 floats (conflict-free frag reads).
// Requires M%128==0, N%128==0, K%16==0.
// ---------------------------------------------------------------------------
__device__ __forceinline__ uint32_t f2tf32(float x) {
    uint32_t y;
    asm volatile("cvt.rna.tf32.f32 %0, %1;" : "=r"(y) : "f"(x));
    return y;
}

__device__ __forceinline__ void mma_tf32(float* c, const uint32_t* a, const uint32_t* b) {
    asm volatile(
        "mma.sync.aligned.m16n8k8.row.col.f32.tf32.tf32.f32 "
        "{%0,%1,%2,%3}, {%4,%5,%6,%7}, {%8,%9}, {%0,%1,%2,%3};"
        : "+f"(c[0]), "+f"(c[1]), "+f"(c[2]), "+f"(c[3])
        : "r"(a[0]), "r"(a[1]), "r"(a[2]), "r"(a[3]), "r"(b[0]), "r"(b[1]));
}

#define LDPAD 136

__global__ __launch_bounds__(256) void gemm_tf32_nt_bias(
    const float* __restrict__ A, const float* __restrict__ Bm,
    const float* __restrict__ bias, float* __restrict__ C,
    int M, int N, int K)
{
    constexpr int BM = 128, BN = 128, BK = 16;
    __shared__ float As[2][BK][LDPAD];
    __shared__ float Bs[2][BK][LDPAD];

    const int tid  = threadIdx.x;
    const int bm   = blockIdx.y * BM;
    const int bn   = blockIdx.x * BN;
    const int lane = tid & 31;
    const int warp = tid >> 5;
    const int wm   = warp >> 1;          // 0..3
    const int wn   = warp & 1;           // 0..1
    const int g    = lane >> 2;          // 0..7
    const int tg   = lane & 3;           // 0..3
    const int m0   = wm * 32;
    const int n0   = wn * 64;

    // loader map: 512 float4 per matrix per tile, 2 per thread
    // idx = tid + 256*r ; row = idx>>2 (0..127), kc = (idx&3)*4
    const int r0row = tid >> 2,          r0kc = (tid & 3) * 4;
    const int r1row = (tid + 256) >> 2,  r1kc = ((tid + 256) & 3) * 4;

    const float* Ap0 = A  + (size_t)(bm + r0row) * K + r0kc;
    const float* Ap1 = A  + (size_t)(bm + r1row) * K + r1kc;
    const float* Bp0 = Bm + (size_t)(bn + r0row) * K + r0kc;
    const float* Bp1 = Bm + (size_t)(bn + r1row) * K + r1kc;

    // ---- preload tile 0
    float4 a40 = *(const float4*)Ap0;
    float4 a41 = *(const float4*)Ap1;
    float4 b40 = *(const float4*)Bp0;
    float4 b41 = *(const float4*)Bp1;
    {
        float* ap = &As[0][r0kc][r0row];
        ap[0*LDPAD] = __uint_as_float(f2tf32(a40.x));
        ap[1*LDPAD] = __uint_as_float(f2tf32(a40.y));
        ap[2*LDPAD] = __uint_as_float(f2tf32(a40.z));
        ap[3*LDPAD] = __uint_as_float(f2tf32(a40.w));
        ap = &As[0][r1kc][r1row];
        ap[0*LDPAD] = __uint_as_float(f2tf32(a41.x));
        ap[1*LDPAD] = __uint_as_float(f2tf32(a41.y));
        ap[2*LDPAD] = __uint_as_float(f2tf32(a41.z));
        ap[3*LDPAD] = __uint_as_float(f2tf32(a41.w));
        float* bp = &Bs[0][r0kc][r0row];
        bp[0*LDPAD] = __uint_as_float(f2tf32(b40.x));
        bp[1*LDPAD] = __uint_as_float(f2tf32(b40.y));
        bp[2*LDPAD] = __uint_as_float(f2tf32(b40.z));
        bp[3*LDPAD] = __uint_as_float(f2tf32(b40.w));
        bp = &Bs[0][r1kc][r1row];
        bp[0*LDPAD] = __uint_as_float(f2tf32(b41.x));
        bp[1*LDPAD] = __uint_as_float(f2tf32(b41.y));
        bp[2*LDPAD] = __uint_as_float(f2tf32(b41.z));
        bp[3*LDPAD] = __uint_as_float(f2tf32(b41.w));
    }
    __syncthreads();

    float acc[2][8][4];
    #pragma unroll
    for (int mt = 0; mt < 2; ++mt)
        #pragma unroll
        for (int nt = 0; nt < 8; ++nt)
            #pragma unroll
            for (int q = 0; q < 4; ++q) acc[mt][nt][q] = 0.f;

    const int NT = K / BK;
    int buf = 0;

    for (int t = 0; t < NT; ++t) {
        if (t + 1 < NT) {
            const int ko = (t + 1) * BK;
            a40 = *(const float4*)(Ap0 + ko);
            a41 = *(const float4*)(Ap1 + ko);
            b40 = *(const float4*)(Bp0 + ko);
            b41 = *(const float4*)(Bp1 + ko);
        }

        #pragma unroll
        for (int ks = 0; ks < 2; ++ks) {
            const int kb = ks * 8;
            uint32_t afr[2][4];
            #pragma unroll
            for (int mt = 0; mt < 2; ++mt) {
                const int mm = m0 + mt * 16 + g;
                afr[mt][0] = __float_as_uint(As[buf][kb + tg    ][mm    ]);
                afr[mt][1] = __float_as_uint(As[buf][kb + tg    ][mm + 8]);
                afr[mt][2] = __float_as_uint(As[buf][kb + tg + 4][mm    ]);
                afr[mt][3] = __float_as_uint(As[buf][kb + tg + 4][mm + 8]);
            }
            uint32_t bfr[8][2];
            #pragma unroll
            for (int nt = 0; nt < 8; ++nt) {
                const int nn = n0 + nt * 8 + g;
                bfr[nt][0] = __float_as_uint(Bs[buf][kb + tg    ][nn]);
                bfr[nt][1] = __float_as_uint(Bs[buf][kb + tg + 4][nn]);
            }
            #pragma unroll
            for (int mt = 0; mt < 2; ++mt)
                #pragma unroll
                for (int nt = 0; nt < 8; ++nt)
                    mma_tf32(acc[mt][nt], afr[mt], bfr[nt]);
        }

        if (t + 1 < NT) {
            const int nb = buf ^ 1;
            float* ap = &As[nb][r0kc][r0row];
            ap[0*LDPAD] = __uint_as_float(f2tf32(a40.x));
            ap[1*LDPAD] = __uint_as_float(f2tf32(a40.y));
            ap[2*LDPAD] = __uint_as_float(f2tf32(a40.z));
            ap[3*LDPAD] = __uint_as_float(f2tf32(a40.w));
            ap = &As[nb][r1kc][r1row];
            ap[0*LDPAD] = __uint_as_float(f2tf32(a41.x));
            ap[1*LDPAD] = __uint_as_float(f2tf32(a41.y));
            ap[2*LDPAD] = __uint_as_float(f2tf32(a41.z));
            ap[3*LDPAD] = __uint_as_float(f2tf32(a41.w));
            float* bp = &Bs[nb][r0kc][r0row];
            bp[0*LDPAD] = __uint_as_float(f2tf32(b40.x));
            bp[1*LDPAD] = __uint_as_float(f2tf32(b40.y));
            bp[2*LDPAD] = __uint_as_float(f2tf32(b40.z));
            bp[3*LDPAD] = __uint_as_float(f2tf32(b40.w));
            bp = &Bs[nb][r1kc][r1row];
            bp[0*LDPAD] = __uint_as_float(f2tf32(b41.x));
            bp[1*LDPAD] = __uint_as_float(f2tf32(b41.y));
            bp[2*LDPAD] = __uint_as_float(f2tf32(b41.z));
            bp[3*LDPAD] = __uint_as_float(f2tf32(b41.w));
        }
        __syncthreads();
        buf ^= 1;
    }

    // epilogue: c layout per 16x8 tile: rows g, g+8; cols 2*tg, 2*tg+1
    #pragma unroll
    for (int mt = 0; mt < 2; ++mt) {
        const int row = bm + m0 + mt * 16 + g;
        #pragma unroll
        for (int nt = 0; nt < 8; ++nt) {
            const int col = bn + n0 + nt * 8 + 2 * tg;
            const float bv0 = bias[col];
            const float bv1 = bias[col + 1];
            float* c0 = C + (size_t)row * N + col;
            float* c1 = C + (size_t)(row + 8) * N + col;
            *(float2*)c0 = make_float2(acc[mt][nt][0] + bv0, acc[mt][nt][1] + bv1);
            *(float2*)c1 = make_float2(acc[mt][nt][2] + bv0, acc[mt][nt][3] + bv1);
        }
    }
}

// ---------------------------------------------------------------------------
// Window attention: one CTA per (window b, head h). 256 threads. (unchanged)
// ---------------------------------------------------------------------------
__global__ __launch_bounds__(256) void win_attn_kernel(
    const float* __restrict__ qkv, const float* __restrict__ table,
    const int* __restrict__ relidx, float* __restrict__ attout)
{
    const int blk = blockIdx.x;
    const int b   = blk >> 4;
    const int h   = blk & 15;
    const int tid = threadIdx.x;

    __shared__ float sq[64][36];
    __shared__ float sk[64][36];
    __shared__ float sv[64][36];
    __shared__ float sp[64][65];
    __shared__ float bias_h[225];
    __shared__ float scale_h[225];

    const size_t base = (size_t)b * NTOK * QKV_COLS + (size_t)h * HD;

    #pragma unroll
    for (int r = 0; r < 2; ++r) {
        const int idx = tid + 256 * r;
        const int row = idx >> 3;
        const int c4  = (idx & 7) * 4;
        const float* gp = qkv + base + (size_t)row * QKV_COLS + c4;
        float4 q4 = *(const float4*)(gp);
        float4 k4 = *(const float4*)(gp + DIMC);
        float4 v4 = *(const float4*)(gp + 2 * DIMC);
        sq[row][c4 + 0] = q4.x; sq[row][c4 + 1] = q4.y;
        sq[row][c4 + 2] = q4.z; sq[row][c4 + 3] = q4.w;
        sk[row][c4 + 0] = k4.x; sk[row][c4 + 1] = k4.y;
        sk[row][c4 + 2] = k4.z; sk[row][c4 + 3] = k4.w;
        sv[row][c4 + 0] = v4.x; sv[row][c4 + 1] = v4.y;
        sv[row][c4 + 2] = v4.z; sv[row][c4 + 3] = v4.w;
    }
    if (tid < 225) {
        bias_h[tid]  = table[tid * (2 * NHEADS) + h];
        scale_h[tid] = table[tid * (2 * NHEADS) + NHEADS + h];
    }
    __syncthreads();

    const int i = tid >> 2;
    const int l = tid & 3;

    float4 qr[8];
    #pragma unroll
    for (int kk = 0; kk < 8; ++kk) qr[kk] = *(const float4*)&sq[i][kk * 4];

    const float scale = 0.17677669529663687f;  // 32^-0.5
    const int* ri = relidx + i * 64;

    float s[16];
    #pragma unroll
    for (int jj = 0; jj < 16; ++jj) {
        const int j = l + jj * 4;
        float acc = 0.f;
        #pragma unroll
        for (int kk = 0; kk < 8; ++kk) {
            const float4 kv = *(const float4*)&sk[j][kk * 4];
            acc += qr[kk].x * kv.x + qr[kk].y * kv.y
                 + qr[kk].z * kv.z + qr[kk].w * kv.w;
        }
        s[jj] = acc * scale + bias_h[ri[j]];
    }

    float mx = s[0];
    #pragma unroll
    for (int jj = 1; jj < 16; ++jj) mx = fmaxf(mx, s[jj]);
    mx = fmaxf(mx, __shfl_xor_sync(0xffffffffu, mx, 1, 4));
    mx = fmaxf(mx, __shfl_xor_sync(0xffffffffu, mx, 2, 4));

    float e[16], sum = 0.f;
    #pragma unroll
    for (int jj = 0; jj < 16; ++jj) { e[jj] = expf(s[jj] - mx); sum += e[jj]; }
    sum += __shfl_xor_sync(0xffffffffu, sum, 1, 4);
    sum += __shfl_xor_sync(0xffffffffu, sum, 2, 4);
    const float inv = 1.f / sum;

    #pragma unroll
    for (int jj = 0; jj < 16; ++jj) {
        const int j = l + jj * 4;
        sp[i][j] = e[jj] * inv * scale_h[ri[j]];
    }
    __syncwarp();

    float o[8] = {0.f, 0.f, 0.f, 0.f, 0.f, 0.f, 0.f, 0.f};
    #pragma unroll
    for (int j = 0; j < 64; ++j) {
        const float p = sp[i][j];
        const float4 v0 = *(const float4*)&sv[j][l * 8];
        const float4 v1 = *(const float4*)&sv[j][l * 8 + 4];
        o[0] += p * v0.x; o[1] += p * v0.y; o[2] += p * v0.z; o[3] += p * v0.w;
        o[4] += p * v1.x; o[5] += p * v1.y; o[6] += p * v1.z; o[7] += p * v1.w;
    }

    float* op = attout + ((size_t)(b * NTOK + i)) * DIMC + h * HD + l * 8;
    *(float4*)(op)     = make_float4(o[0], o[1], o[2], o[3]);
    *(float4*)(op + 4) = make_float4(o[4], o[5], o[6], o[7]);
}

// ---------------------------------------------------------------------------
// Launch
// ---------------------------------------------------------------------------
extern "C" void kernel_launch(void* const* d_in, const int* in_sizes, int n_in,
                              void* d_out, int out_size)
{
    const float* x      = (const float*)d_in[0];
    const float* qkv_w  = (const float*)d_in[1];
    const float* qkv_b  = (const float*)d_in[2];
    const float* proj_w = (const float*)d_in[3];
    const float* proj_b = (const float*)d_in[4];
    const float* table  = (const float*)d_in[5];
    const int*   relidx = (const int*)d_in[6];
    float*       out    = (float*)d_out;

    float* qkvbuf = nullptr;
    float* attbuf = nullptr;
    cudaGetSymbolAddress((void**)&qkvbuf, g_qkv);
    cudaGetSymbolAddress((void**)&attbuf, g_att);

    // 1) QKV GEMM: [65536,512] x [1536,512]^T -> [65536,1536]
    gemm_tf32_nt_bias<<<dim3(QKV_COLS / 128, MTOT / 128), 256>>>(
        x, qkv_w, qkv_b, qkvbuf, MTOT, QKV_COLS, DIMC);

    // 2) windowed attention: one CTA per (window, head)
    win_attn_kernel<<<NWIN * NHEADS, 256>>>(qkvbuf, table, relidx, attbuf);

    // 3) projection GEMM: [65536,512] x [512,512]^T -> out
    gemm_tf32_nt_bias<<<dim3(DIMC / 128, MTOT / 128), 256>>>(
        attbuf, proj_w, proj_b, out, MTOT, DIMC, DIMC);
}

// round 5
// speedup vs baseline: 2.9073x; 1.5620x over previous
#include <cuda_runtime.h>
#include <cuda_bf16.h>
#include <cstdint>
#include <cstddef>

// ---------------------------------------------------------------------------
// Problem constants
// ---------------------------------------------------------------------------
#define DIMC     512
#define NHEADS   16
#define HD       32
#define NTOK     64
#define NWIN     1024
#define MTOT     (NWIN * NTOK)      // 65536
#define QKV_COLS (3 * DIMC)         // 1536

// Scratch (device globals: allocation rules forbid cudaMalloc)
__device__ __nv_bfloat16 g_xb  [(size_t)MTOT * DIMC];       // 67 MB
__device__ __nv_bfloat16 g_qkv [(size_t)MTOT * QKV_COLS];   // 201 MB
__device__ __nv_bfloat16 g_att [(size_t)MTOT * DIMC];       // 67 MB
__device__ __nv_bfloat16 g_wqkv[(size_t)QKV_COLS * DIMC];   // 1.5 MB
__device__ __nv_bfloat16 g_wprj[(size_t)DIMC * DIMC];       // 0.5 MB

// ---------------------------------------------------------------------------
// Helpers
// ---------------------------------------------------------------------------
__device__ __forceinline__ uint32_t smem_u32(const void* p) {
    uint32_t a;
    asm("{ .reg .u64 t; cvta.to.shared.u64 t, %1; cvt.u32.u64 %0, t; }"
        : "=r"(a) : "l"(p));
    return a;
}
#define CP_ASYNC16(dst, src) \
    asm volatile("cp.async.cg.shared.global [%0], [%1], 16;" :: "r"(dst), "l"(src))
#define CP_COMMIT() asm volatile("cp.async.commit_group;" ::: "memory")
#define CP_WAIT0()  asm volatile("cp.async.wait_group 0;" ::: "memory")
#define CP_WAIT1()  asm volatile("cp.async.wait_group 1;" ::: "memory")

#define LDSM_X4(r0, r1, r2, r3, a) \
    asm volatile("ldmatrix.sync.aligned.m8n8.x4.shared.b16 {%0,%1,%2,%3}, [%4];" \
        : "=r"(r0), "=r"(r1), "=r"(r2), "=r"(r3) : "r"(a))

__device__ __forceinline__ void mma_bf16(float* c, const uint32_t* a, const uint32_t* b) {
    asm volatile(
        "mma.sync.aligned.m16n8k16.row.col.f32.bf16.bf16.f32 "
        "{%0,%1,%2,%3}, {%4,%5,%6,%7}, {%8,%9}, {%0,%1,%2,%3};"
        : "+f"(c[0]), "+f"(c[1]), "+f"(c[2]), "+f"(c[3])
        : "r"(a[0]), "r"(a[1]), "r"(a[2]), "r"(a[3]), "r"(b[0]), "r"(b[1]));
}

__device__ __forceinline__ uint32_t pk2(float x, float y) {
    __nv_bfloat162 t = __floats2bfloat162_rn(x, y);
    return *reinterpret_cast<uint32_t*>(&t);
}
__device__ __forceinline__ void unp8(uint4 u, float* f) {
    float2 t;
    t = __bfloat1622float2(*reinterpret_cast<__nv_bfloat162*>(&u.x)); f[0] = t.x; f[1] = t.y;
    t = __bfloat1622float2(*reinterpret_cast<__nv_bfloat162*>(&u.y)); f[2] = t.x; f[3] = t.y;
    t = __bfloat1622float2(*reinterpret_cast<__nv_bfloat162*>(&u.z)); f[4] = t.x; f[5] = t.y;
    t = __bfloat1622float2(*reinterpret_cast<__nv_bfloat162*>(&u.w)); f[6] = t.x; f[7] = t.y;
}

// ---------------------------------------------------------------------------
// f32 -> bf16 convert (8 elems / thread)
// ---------------------------------------------------------------------------
__global__ void cvt_bf16(const float* __restrict__ in, __nv_bfloat16* __restrict__ out,
                         int n8) {
    int i = blockIdx.x * blockDim.x + threadIdx.x;
    if (i >= n8) return;
    const float4* p = (const float4*)in + 2 * (size_t)i;
    float4 a = p[0], b = p[1];
    uint4 o;
    o.x = pk2(a.x, a.y); o.y = pk2(a.z, a.w);
    o.z = pk2(b.x, b.y); o.w = pk2(b.z, b.w);
    ((uint4*)out)[i] = o;
}

// ---------------------------------------------------------------------------
// bf16 mma.sync GEMM (NT): C[M,N] = A[M,K]*B[N,K]^T + bias[N]
// BM=128, BN=128, BK=32, K=512. 256 threads (8 warps), warp tile 32x64.
// mma.m16n8k16 + ldmatrix.x4; cp.async 2-stage pipeline.
// smem rows padded to 144B -> ldmatrix & stores conflict-light.
// ---------------------------------------------------------------------------
#define BM 128
#define BN 128
#define BK 32
#define NT_TILES (DIMC / BK)         // 16
#define ROWB 144                     // bytes per padded smem row (72 bf16)
#define STG_A (BM * ROWB)            // 18432
#define STG_B (BN * ROWB)            // 18432
#define OFF_B (2 * STG_A)            // A stages at 0, STG_A; B at OFF_B, OFF_B+STG_B
#define SMEM_BYTES (2 * STG_A + 2 * STG_B)   // 73728

template <bool OBF>
__global__ __launch_bounds__(256) void gemm_bf16mma(
    const __nv_bfloat16* __restrict__ A, const __nv_bfloat16* __restrict__ Bw,
    const float* __restrict__ bias, void* __restrict__ Cout, int N)
{
    extern __shared__ char smem[];
    const uint32_t sb = smem_u32(smem);
    const int tid  = threadIdx.x;
    const int lane = tid & 31;
    const int warp = tid >> 5;
    const int m0   = (warp & 3) * 32;     // warp m origin
    const int n0   = (warp >> 2) * 64;    // warp n origin
    const int bm   = blockIdx.y * BM;
    const int bn   = blockIdx.x * BN;

    // loader map: row = tid>>1 (0..127), 2 x 16B granules at (tid&1)*2
    const int lrow = tid >> 1;
    const int lgc  = (tid & 1) * 2;
    const __nv_bfloat16* Ag = A  + (size_t)(bm + lrow) * DIMC + lgc * 8;
    const __nv_bfloat16* Bg = Bw + (size_t)(bn + lrow) * DIMC + lgc * 8;
    const uint32_t daBase = sb + lrow * ROWB + lgc * 16;

    // prologue: stages 0,1
    #pragma unroll
    for (int st = 0; st < 2; ++st) {
        const uint32_t da = daBase + st * STG_A;
        const uint32_t db = daBase + OFF_B + st * STG_B;
        CP_ASYNC16(da,      Ag + st * BK);
        CP_ASYNC16(da + 16, Ag + st * BK + 8);
        CP_ASYNC16(db,      Bg + st * BK);
        CP_ASYNC16(db + 16, Bg + st * BK + 8);
        CP_COMMIT();
    }

    float acc[2][8][4];
    #pragma unroll
    for (int mt = 0; mt < 2; ++mt)
        #pragma unroll
        for (int nt = 0; nt < 8; ++nt)
            #pragma unroll
            for (int q = 0; q < 4; ++q) acc[mt][nt][q] = 0.f;

    // ldmatrix base offsets (per lane)
    const int aRow = (lane & 15);
    const int aColB = ((lane >> 4) << 3) * 2;          // bytes
    const int bRow = (lane & 7) + ((lane >> 4) << 3);
    const int bColB = (((lane >> 3) & 1) << 3) * 2;    // bytes

    for (int t = 0; t < NT_TILES; ++t) {
        if (t + 2 < NT_TILES) { CP_WAIT1(); } else { CP_WAIT0(); }
        __syncthreads();

        const int buf = t & 1;
        const uint32_t sA = sb + buf * STG_A;
        const uint32_t sB = sb + OFF_B + buf * STG_B;

        #pragma unroll
        for (int ks = 0; ks < 2; ++ks) {
            const int kbB = ks * 32;  // 16 bf16 = 32 bytes
            uint32_t af[2][4];
            #pragma unroll
            for (int mt = 0; mt < 2; ++mt)
                LDSM_X4(af[mt][0], af[mt][1], af[mt][2], af[mt][3],
                        sA + (m0 + mt * 16 + aRow) * ROWB + kbB + aColB);
            uint32_t bf[8][2];
            #pragma unroll
            for (int np = 0; np < 4; ++np) {
                uint32_t r0, r1, r2, r3;
                LDSM_X4(r0, r1, r2, r3,
                        sB + (n0 + np * 16 + bRow) * ROWB + kbB + bColB);
                bf[2*np][0] = r0; bf[2*np][1] = r1;
                bf[2*np+1][0] = r2; bf[2*np+1][1] = r3;
            }
            #pragma unroll
            for (int mt = 0; mt < 2; ++mt)
                #pragma unroll
                for (int nt = 0; nt < 8; ++nt)
                    mma_bf16(acc[mt][nt], af[mt], bf[nt]);
        }
        __syncthreads();

        if (t + 2 < NT_TILES) {
            const int st = t + 2;
            const uint32_t da = daBase + buf * STG_A;
            const uint32_t db = daBase + OFF_B + buf * STG_B;
            CP_ASYNC16(da,      Ag + st * BK);
            CP_ASYNC16(da + 16, Ag + st * BK + 8);
            CP_ASYNC16(db,      Bg + st * BK);
            CP_ASYNC16(db + 16, Bg + st * BK + 8);
            CP_COMMIT();
        }
    }

    // epilogue: c0,c1 -> row m0+mt*16+lane/4, cols n+2*(lane%4); c2,c3 -> row+8
    const int erow = lane >> 2;
    const int ecol = (lane & 3) * 2;
    #pragma unroll
    for (int mt = 0; mt < 2; ++mt) {
        const int r0 = bm + m0 + mt * 16 + erow;
        #pragma unroll
        for (int nt = 0; nt < 8; ++nt) {
            const int c = bn + n0 + nt * 8 + ecol;
            const float b0 = bias[c], b1 = bias[c + 1];
            if (OBF) {
                __nv_bfloat16* C = (__nv_bfloat16*)Cout;
                *(uint32_t*)(C + (size_t)r0 * N + c) =
                    pk2(acc[mt][nt][0] + b0, acc[mt][nt][1] + b1);
                *(uint32_t*)(C + (size_t)(r0 + 8) * N + c) =
                    pk2(acc[mt][nt][2] + b0, acc[mt][nt][3] + b1);
            } else {
                float* C = (float*)Cout;
                *(float2*)(C + (size_t)r0 * N + c) =
                    make_float2(acc[mt][nt][0] + b0, acc[mt][nt][1] + b1);
                *(float2*)(C + (size_t)(r0 + 8) * N + c) =
                    make_float2(acc[mt][nt][2] + b0, acc[mt][nt][3] + b1);
            }
        }
    }
}

// ---------------------------------------------------------------------------
// Window attention: one CTA per (window b, head h). 256 threads. bf16 I/O.
// ---------------------------------------------------------------------------
__global__ __launch_bounds__(256) void win_attn(
    const __nv_bfloat16* __restrict__ qkv, const float* __restrict__ table,
    const int* __restrict__ relidx, __nv_bfloat16* __restrict__ attout)
{
    const int blk = blockIdx.x;
    const int b   = blk >> 4;
    const int h   = blk & 15;
    const int tid = threadIdx.x;

    __shared__ float sq[64][36];
    __shared__ float sk[64][36];
    __shared__ float sv[64][36];
    __shared__ float sp[64][65];
    __shared__ float bias_h[225];
    __shared__ float scale_h[225];

    const size_t base = (size_t)b * NTOK * QKV_COLS + (size_t)h * HD;

    {
        const int row = tid >> 2;
        const int c8  = (tid & 3) * 8;
        const __nv_bfloat16* gp = qkv + base + (size_t)row * QKV_COLS + c8;
        uint4 q4 = *(const uint4*)(gp);
        uint4 k4 = *(const uint4*)(gp + DIMC);
        uint4 v4 = *(const uint4*)(gp + 2 * DIMC);
        unp8(q4, &sq[row][c8]);
        unp8(k4, &sk[row][c8]);
        unp8(v4, &sv[row][c8]);
    }
    if (tid < 225) {
        bias_h[tid]  = table[tid * (2 * NHEADS) + h];
        scale_h[tid] = table[tid * (2 * NHEADS) + NHEADS + h];
    }
    __syncthreads();

    const int i = tid >> 2;
    const int l = tid & 3;

    float4 qr[8];
    #pragma unroll
    for (int kk = 0; kk < 8; ++kk) qr[kk] = *(const float4*)&sq[i][kk * 4];

    const float scale = 0.17677669529663687f;  // 32^-0.5
    const int* ri = relidx + i * 64;

    float s[16];
    #pragma unroll
    for (int jj = 0; jj < 16; ++jj) {
        const int j = l + jj * 4;
        float acc = 0.f;
        #pragma unroll
        for (int kk = 0; kk < 8; ++kk) {
            const float4 kv = *(const float4*)&sk[j][kk * 4];
            acc += qr[kk].x * kv.x + qr[kk].y * kv.y
                 + qr[kk].z * kv.z + qr[kk].w * kv.w;
        }
        s[jj] = acc * scale + bias_h[ri[j]];
    }

    float mx = s[0];
    #pragma unroll
    for (int jj = 1; jj < 16; ++jj) mx = fmaxf(mx, s[jj]);
    mx = fmaxf(mx, __shfl_xor_sync(0xffffffffu, mx, 1, 4));
    mx = fmaxf(mx, __shfl_xor_sync(0xffffffffu, mx, 2, 4));

    float e[16], sum = 0.f;
    #pragma unroll
    for (int jj = 0; jj < 16; ++jj) { e[jj] = expf(s[jj] - mx); sum += e[jj]; }
    sum += __shfl_xor_sync(0xffffffffu, sum, 1, 4);
    sum += __shfl_xor_sync(0xffffffffu, sum, 2, 4);
    const float inv = 1.f / sum;

    #pragma unroll
    for (int jj = 0; jj < 16; ++jj) {
        const int j = l + jj * 4;
        sp[i][j] = e[jj] * inv * scale_h[ri[j]];
    }
    __syncwarp();

    float o[8] = {0.f, 0.f, 0.f, 0.f, 0.f, 0.f, 0.f, 0.f};
    #pragma unroll
    for (int j = 0; j < 64; ++j) {
        const float p = sp[i][j];
        const float4 v0 = *(const float4*)&sv[j][l * 8];
        const float4 v1 = *(const float4*)&sv[j][l * 8 + 4];
        o[0] += p * v0.x; o[1] += p * v0.y; o[2] += p * v0.z; o[3] += p * v0.w;
        o[4] += p * v1.x; o[5] += p * v1.y; o[6] += p * v1.z; o[7] += p * v1.w;
    }

    uint4 ov;
    ov.x = pk2(o[0], o[1]); ov.y = pk2(o[2], o[3]);
    ov.z = pk2(o[4], o[5]); ov.w = pk2(o[6], o[7]);
    *(uint4*)(attout + ((size_t)(b * NTOK + i)) * DIMC + h * HD + l * 8) = ov;
}

// ---------------------------------------------------------------------------
// Launch
// ---------------------------------------------------------------------------
extern "C" void kernel_launch(void* const* d_in, const int* in_sizes, int n_in,
                              void* d_out, int out_size)
{
    const float* x      = (const float*)d_in[0];
    const float* qkv_w  = (const float*)d_in[1];
    const float* qkv_b  = (const float*)d_in[2];
    const float* proj_w = (const float*)d_in[3];
    const float* proj_b = (const float*)d_in[4];
    const float* table  = (const float*)d_in[5];
    const int*   relidx = (const int*)d_in[6];
    float*       out    = (float*)d_out;

    __nv_bfloat16 *xb, *qkvb, *attb, *wq, *wp;
    cudaGetSymbolAddress((void**)&xb,   g_xb);
    cudaGetSymbolAddress((void**)&qkvb, g_qkv);
    cudaGetSymbolAddress((void**)&attb, g_att);
    cudaGetSymbolAddress((void**)&wq,   g_wqkv);
    cudaGetSymbolAddress((void**)&wp,   g_wprj);

    cudaFuncSetAttribute(gemm_bf16mma<true>,
        cudaFuncAttributeMaxDynamicSharedMemorySize, SMEM_BYTES);
    cudaFuncSetAttribute(gemm_bf16mma<false>,
        cudaFuncAttributeMaxDynamicSharedMemorySize, SMEM_BYTES);

    // 0) bf16 conversions
    const int nx = MTOT * DIMC / 8;
    cvt_bf16<<<(nx + 255) / 256, 256>>>(x, xb, nx);
    const int nwq = QKV_COLS * DIMC / 8;
    cvt_bf16<<<(nwq + 255) / 256, 256>>>(qkv_w, wq, nwq);
    const int nwp = DIMC * DIMC / 8;
    cvt_bf16<<<(nwp + 255) / 256, 256>>>(proj_w, wp, nwp);

    // 1) QKV GEMM: [65536,512] x [1536,512]^T -> bf16 [65536,1536]
    gemm_bf16mma<true><<<dim3(QKV_COLS / BN, MTOT / BM), 256, SMEM_BYTES>>>(
        xb, wq, qkv_b, qkvb, QKV_COLS);

    // 2) windowed attention
    win_attn<<<NWIN * NHEADS, 256>>>(qkvb, table, relidx, attb);

    // 3) projection GEMM: [65536,512] x [512,512]^T -> f32 out
    gemm_bf16mma<false><<<dim3(DIMC / BN, MTOT / BM), 256, SMEM_BYTES>>>(
        attb, wp, proj_b, out, DIMC);
}

// round 6
// speedup vs baseline: 4.3143x; 1.4839x over previous
#include <cuda_runtime.h>
#include <cuda_bf16.h>
#include <cstdint>
#include <cstddef>

// ---------------------------------------------------------------------------
// Problem constants
// ---------------------------------------------------------------------------
#define DIMC     512
#define NHEADS   16
#define HD       32
#define NTOK     64
#define NWIN     1024
#define MTOT     (NWIN * NTOK)      // 65536
#define QKV_COLS (3 * DIMC)         // 1536

// Scratch (device globals: allocation rules forbid cudaMalloc)
__device__ __nv_bfloat16 g_xb  [(size_t)MTOT * DIMC];
__device__ __nv_bfloat16 g_qkv [(size_t)MTOT * QKV_COLS];
__device__ __nv_bfloat16 g_att [(size_t)MTOT * DIMC];
__device__ __nv_bfloat16 g_wqkv[(size_t)QKV_COLS * DIMC];
__device__ __nv_bfloat16 g_wprj[(size_t)DIMC * DIMC];

// ---------------------------------------------------------------------------
// Helpers
// ---------------------------------------------------------------------------
__device__ __forceinline__ uint32_t smem_u32(const void* p) {
    uint32_t a;
    asm("{ .reg .u64 t; cvta.to.shared.u64 t, %1; cvt.u32.u64 %0, t; }"
        : "=r"(a) : "l"(p));
    return a;
}
#define CP_ASYNC16(dst, src) \
    asm volatile("cp.async.cg.shared.global [%0], [%1], 16;" :: "r"(dst), "l"(src))
#define CP_COMMIT() asm volatile("cp.async.commit_group;" ::: "memory")
#define CP_WAIT0()  asm volatile("cp.async.wait_group 0;" ::: "memory")
#define CP_WAIT2()  asm volatile("cp.async.wait_group 2;" ::: "memory")

#define LDSM_X4(r0, r1, r2, r3, a) \
    asm volatile("ldmatrix.sync.aligned.m8n8.x4.shared.b16 {%0,%1,%2,%3}, [%4];" \
        : "=r"(r0), "=r"(r1), "=r"(r2), "=r"(r3) : "r"(a))
#define LDSM_X4T(r0, r1, r2, r3, a) \
    asm volatile("ldmatrix.sync.aligned.m8n8.x4.trans.shared.b16 {%0,%1,%2,%3}, [%4];" \
        : "=r"(r0), "=r"(r1), "=r"(r2), "=r"(r3) : "r"(a))

__device__ __forceinline__ void mma_bf16(float* c, const uint32_t* a, const uint32_t* b) {
    asm volatile(
        "mma.sync.aligned.m16n8k16.row.col.f32.bf16.bf16.f32 "
        "{%0,%1,%2,%3}, {%4,%5,%6,%7}, {%8,%9}, {%0,%1,%2,%3};"
        : "+f"(c[0]), "+f"(c[1]), "+f"(c[2]), "+f"(c[3])
        : "r"(a[0]), "r"(a[1]), "r"(a[2]), "r"(a[3]), "r"(b[0]), "r"(b[1]));
}

__device__ __forceinline__ uint32_t pk2(float x, float y) {
    __nv_bfloat162 t = __floats2bfloat162_rn(x, y);
    return *reinterpret_cast<uint32_t*>(&t);
}

// ---------------------------------------------------------------------------
// f32 -> bf16 convert (8 elems / thread)
// ---------------------------------------------------------------------------
__global__ void cvt_bf16(const float* __restrict__ in, __nv_bfloat16* __restrict__ out,
                         int n8) {
    int i = blockIdx.x * blockDim.x + threadIdx.x;
    if (i >= n8) return;
    const float4* p = (const float4*)in + 2 * (size_t)i;
    float4 a = p[0], b = p[1];
    uint4 o;
    o.x = pk2(a.x, a.y); o.y = pk2(a.z, a.w);
    o.z = pk2(b.x, b.y); o.w = pk2(b.z, b.w);
    ((uint4*)out)[i] = o;
}

// ---------------------------------------------------------------------------
// bf16 mma.sync GEMM (NT): C[M,N] = A[M,K]*B[N,K]^T + bias[N]
// BM=BN=128, BK=16, K=512 -> 32 iterations; 4-stage cp.async pipeline with
// ONE __syncthreads per iteration. 8 warps, warp tile 32x64.
// smem row stride 48B (granule pattern 3r mod 8 -> conflict-free ldmatrix).
// ---------------------------------------------------------------------------
#define BM 128
#define BN 128
#define BK 16
#define NT_TILES (DIMC / BK)     // 32
#define ROWB 48                  // bytes per smem row (32B data + 16B pad)
#define MATB (128 * ROWB)        // 6144 per matrix per stage
#define STGB (2 * MATB)          // 12288 per stage
#define SMEM_GEMM (4 * STGB)     // 49152

template <bool OBF>
__global__ __launch_bounds__(256) void gemm_bf16mma(
    const __nv_bfloat16* __restrict__ A, const __nv_bfloat16* __restrict__ Bw,
    const float* __restrict__ bias, void* __restrict__ Cout, int N)
{
    extern __shared__ char smem[];
    const uint32_t sb = smem_u32(smem);
    const int tid  = threadIdx.x;
    const int lane = tid & 31;
    const int warp = tid >> 5;
    const int m0   = (warp & 3) * 32;
    const int n0   = (warp >> 2) * 64;
    const int bm   = blockIdx.y * BM;
    const int bn   = blockIdx.x * BN;

    // loader: tids 0-127 -> A row tid; tids 128-255 -> B row tid-128
    const int lmat = tid >> 7;
    const int lrow = tid & 127;
    const __nv_bfloat16* gsrc = lmat
        ? (Bw + (size_t)(bn + lrow) * DIMC)
        : (A  + (size_t)(bm + lrow) * DIMC);
    const uint32_t ldst = sb + lmat * MATB + lrow * ROWB;

    // prologue: stages 0..2
    #pragma unroll
    for (int st = 0; st < 3; ++st) {
        const uint32_t d = ldst + st * STGB;
        CP_ASYNC16(d,      gsrc + st * BK);
        CP_ASYNC16(d + 16, gsrc + st * BK + 8);
        CP_COMMIT();
    }

    float acc[2][8][4];
    #pragma unroll
    for (int mt = 0; mt < 2; ++mt)
        #pragma unroll
        for (int nt = 0; nt < 8; ++nt)
            #pragma unroll
            for (int q = 0; q < 4; ++q) acc[mt][nt][q] = 0.f;

    const int aRow  = lane & 15;
    const int aColB = (lane >> 4) * 16;
    const int bRow  = (lane & 7) + ((lane >> 4) << 3);
    const int bColB = ((lane >> 3) & 1) * 16;

    for (int t = 0; t < NT_TILES; ++t) {
        if (t + 3 < NT_TILES) { CP_WAIT2(); } else { CP_WAIT0(); }
        __syncthreads();

        const uint32_t sA = sb + (t & 3) * STGB;
        const uint32_t sB = sA + MATB;

        uint32_t af[2][4];
        #pragma unroll
        for (int mt = 0; mt < 2; ++mt)
            LDSM_X4(af[mt][0], af[mt][1], af[mt][2], af[mt][3],
                    sA + (m0 + mt * 16 + aRow) * ROWB + aColB);
        uint32_t bf[8][2];
        #pragma unroll
        for (int np = 0; np < 4; ++np) {
            uint32_t r0, r1, r2, r3;
            LDSM_X4(r0, r1, r2, r3,
                    sB + (n0 + np * 16 + bRow) * ROWB + bColB);
            bf[2*np][0] = r0; bf[2*np][1] = r1;
            bf[2*np+1][0] = r2; bf[2*np+1][1] = r3;
        }
        #pragma unroll
        for (int mt = 0; mt < 2; ++mt)
            #pragma unroll
            for (int nt = 0; nt < 8; ++nt)
                mma_bf16(acc[mt][nt], af[mt], bf[nt]);

        if (t + 3 < NT_TILES) {
            const int st = t + 3;
            const uint32_t d = ldst + (st & 3) * STGB;
            CP_ASYNC16(d,      gsrc + st * BK);
            CP_ASYNC16(d + 16, gsrc + st * BK + 8);
            CP_COMMIT();
        }
    }

    // epilogue
    const int erow = lane >> 2;
    const int ecol = (lane & 3) * 2;
    #pragma unroll
    for (int mt = 0; mt < 2; ++mt) {
        const int r0 = bm + m0 + mt * 16 + erow;
        #pragma unroll
        for (int nt = 0; nt < 8; ++nt) {
            const int c = bn + n0 + nt * 8 + ecol;
            const float b0 = bias[c], b1 = bias[c + 1];
            if (OBF) {
                __nv_bfloat16* C = (__nv_bfloat16*)Cout;
                *(uint32_t*)(C + (size_t)r0 * N + c) =
                    pk2(acc[mt][nt][0] + b0, acc[mt][nt][1] + b1);
                *(uint32_t*)(C + (size_t)(r0 + 8) * N + c) =
                    pk2(acc[mt][nt][2] + b0, acc[mt][nt][3] + b1);
            } else {
                float* C = (float*)Cout;
                *(float2*)(C + (size_t)r0 * N + c) =
                    make_float2(acc[mt][nt][0] + b0, acc[mt][nt][1] + b1);
                *(float2*)(C + (size_t)(r0 + 8) * N + c) =
                    make_float2(acc[mt][nt][2] + b0, acc[mt][nt][3] + b1);
            }
        }
    }
}

// ---------------------------------------------------------------------------
// Tensor-core window attention.
// One CTA = (window, head-pair). 8 warps; warp w: head = w>>2, m-tile = w&3.
// QK^T and PV via m16n8k16; softmax on C fragments (4-lane row groups).
// Q/K/V tiles [64 x 32] bf16 in smem, row stride 80B (conflict-free ldmatrix).
// ---------------------------------------------------------------------------
#define SROW 40   // bf16 elements per smem row (80 bytes)

__global__ __launch_bounds__(256) void win_attn_mma(
    const __nv_bfloat16* __restrict__ qkv, const float* __restrict__ table,
    const int* __restrict__ relidx, __nv_bfloat16* __restrict__ attout)
{
    const int blk  = blockIdx.x;       // 0..8191
    const int b    = blk >> 3;
    const int hp   = blk & 7;          // head pair
    const int tid  = threadIdx.x;
    const int lane = tid & 31;
    const int warp = tid >> 5;
    const int hh   = warp >> 2;        // head within pair
    const int wm   = warp & 3;         // m-tile (16 rows)
    const int h    = hp * 2 + hh;

    __shared__ __nv_bfloat16 sq[2][64 * SROW];
    __shared__ __nv_bfloat16 sk[2][64 * SROW];
    __shared__ __nv_bfloat16 sv[2][64 * SROW];
    __shared__ float tb[2][226], ts[2][226];
    __shared__ unsigned char sri[4096];

    // ---- load q,k,v for both heads (uint4 = 8 bf16)
    {
        const int row = tid >> 2;
        const int seg = (tid & 3) * 8;
        #pragma unroll
        for (int e = 0; e < 2; ++e) {
            const __nv_bfloat16* gp = qkv + ((size_t)(b * 64 + row)) * QKV_COLS
                                    + (hp * 2 + e) * HD + seg;
            *(uint4*)&sq[e][row * SROW + seg] = *(const uint4*)(gp);
            *(uint4*)&sk[e][row * SROW + seg] = *(const uint4*)(gp + DIMC);
            *(uint4*)&sv[e][row * SROW + seg] = *(const uint4*)(gp + 2 * DIMC);
        }
    }
    for (int i = tid; i < 4096; i += 256) sri[i] = (unsigned char)relidx[i];
    if (tid < 225) {
        tb[0][tid] = table[tid * (2 * NHEADS) + hp * 2];
        ts[0][tid] = table[tid * (2 * NHEADS) + NHEADS + hp * 2];
        tb[1][tid] = table[tid * (2 * NHEADS) + hp * 2 + 1];
        ts[1][tid] = table[tid * (2 * NHEADS) + NHEADS + hp * 2 + 1];
    }
    __syncthreads();

    const uint32_t sqb = smem_u32(&sq[hh][0]);
    const uint32_t skb = smem_u32(&sk[hh][0]);
    const uint32_t svb = smem_u32(&sv[hh][0]);

    // ---- S = Q K^T  (M=16 rows of this warp, N=64, K=32)
    float acc[8][4];
    #pragma unroll
    for (int nt = 0; nt < 8; ++nt)
        #pragma unroll
        for (int q = 0; q < 4; ++q) acc[nt][q] = 0.f;

    const int aRow  = lane & 15;
    const int aColB = (lane >> 4) * 16;
    const int bRow  = (lane & 7) + ((lane >> 4) << 3);
    const int bColB = ((lane >> 3) & 1) * 16;

    #pragma unroll
    for (int ks = 0; ks < 2; ++ks) {
        uint32_t af[4];
        LDSM_X4(af[0], af[1], af[2], af[3],
                sqb + (wm * 16 + aRow) * 80 + ks * 32 + aColB);
        #pragma unroll
        for (int np = 0; np < 4; ++np) {
            uint32_t r0, r1, r2, r3;
            LDSM_X4(r0, r1, r2, r3,
                    skb + (np * 16 + bRow) * 80 + ks * 32 + bColB);
            uint32_t b0[2] = {r0, r1}, b1[2] = {r2, r3};
            mma_bf16(acc[2 * np],     af, b0);
            mma_bf16(acc[2 * np + 1], af, b1);
        }
    }

    // ---- softmax on fragments (rows i0 = wm*16+erow, i1 = i0+8)
    const int erow = lane >> 2;
    const int tg   = lane & 3;
    const int i0   = wm * 16 + erow;
    const int i1   = i0 + 8;
    const float qs = 0.17677669529663687f;  // 32^-0.5

    float s0[16], s1[16];
    #pragma unroll
    for (int nt = 0; nt < 8; ++nt) {
        const int c0 = nt * 8 + 2 * tg;
        s0[2*nt]   = acc[nt][0] * qs + tb[hh][sri[i0 * 64 + c0]];
        s0[2*nt+1] = acc[nt][1] * qs + tb[hh][sri[i0 * 64 + c0 + 1]];
        s1[2*nt]   = acc[nt][2] * qs + tb[hh][sri[i1 * 64 + c0]];
        s1[2*nt+1] = acc[nt][3] * qs + tb[hh][sri[i1 * 64 + c0 + 1]];
    }
    float m0v = s0[0], m1v = s1[0];
    #pragma unroll
    for (int j = 1; j < 16; ++j) { m0v = fmaxf(m0v, s0[j]); m1v = fmaxf(m1v, s1[j]); }
    m0v = fmaxf(m0v, __shfl_xor_sync(0xffffffffu, m0v, 1));
    m0v = fmaxf(m0v, __shfl_xor_sync(0xffffffffu, m0v, 2));
    m1v = fmaxf(m1v, __shfl_xor_sync(0xffffffffu, m1v, 1));
    m1v = fmaxf(m1v, __shfl_xor_sync(0xffffffffu, m1v, 2));

    float sum0 = 0.f, sum1 = 0.f;
    #pragma unroll
    for (int j = 0; j < 16; ++j) {
        s0[j] = expf(s0[j] - m0v); sum0 += s0[j];
        s1[j] = expf(s1[j] - m1v); sum1 += s1[j];
    }
    sum0 += __shfl_xor_sync(0xffffffffu, sum0, 1);
    sum0 += __shfl_xor_sync(0xffffffffu, sum0, 2);
    sum1 += __shfl_xor_sync(0xffffffffu, sum1, 1);
    sum1 += __shfl_xor_sync(0xffffffffu, sum1, 2);
    const float inv0 = 1.f / sum0, inv1 = 1.f / sum1;

    #pragma unroll
    for (int nt = 0; nt < 8; ++nt) {
        const int c0 = nt * 8 + 2 * tg;
        s0[2*nt]   *= inv0 * ts[hh][sri[i0 * 64 + c0]];
        s0[2*nt+1] *= inv0 * ts[hh][sri[i0 * 64 + c0 + 1]];
        s1[2*nt]   *= inv1 * ts[hh][sri[i1 * 64 + c0]];
        s1[2*nt+1] *= inv1 * ts[hh][sri[i1 * 64 + c0 + 1]];
    }

    // ---- P fragments (A operand), 4 k16-tiles over the 64 tokens
    uint32_t pa[4][4];
    #pragma unroll
    for (int kt = 0; kt < 4; ++kt) {
        pa[kt][0] = pk2(s0[4*kt],   s0[4*kt+1]);
        pa[kt][1] = pk2(s1[4*kt],   s1[4*kt+1]);
        pa[kt][2] = pk2(s0[4*kt+2], s0[4*kt+3]);
        pa[kt][3] = pk2(s1[4*kt+2], s1[4*kt+3]);
    }

    // ---- O = P V  (N = hd = 32 -> 4 n-tiles)
    float o[4][4];
    #pragma unroll
    for (int nt = 0; nt < 4; ++nt)
        #pragma unroll
        for (int q = 0; q < 4; ++q) o[nt][q] = 0.f;

    #pragma unroll
    for (int kt = 0; kt < 4; ++kt) {
        #pragma unroll
        for (int j = 0; j < 2; ++j) {
            uint32_t r0, r1, r2, r3;
            LDSM_X4T(r0, r1, r2, r3,
                     svb + (kt * 16 + (lane & 15)) * 80 + j * 32 + (lane >> 4) * 16);
            uint32_t b0[2] = {r0, r1}, b1[2] = {r2, r3};
            mma_bf16(o[2 * j],     pa[kt], b0);
            mma_bf16(o[2 * j + 1], pa[kt], b1);
        }
    }

    // ---- store O (bf16)
    #pragma unroll
    for (int nt = 0; nt < 4; ++nt) {
        const int col = h * HD + nt * 8 + 2 * tg;
        *(uint32_t*)(attout + ((size_t)(b * 64 + i0)) * DIMC + col) =
            pk2(o[nt][0], o[nt][1]);
        *(uint32_t*)(attout + ((size_t)(b * 64 + i1)) * DIMC + col) =
            pk2(o[nt][2], o[nt][3]);
    }
}

// ---------------------------------------------------------------------------
// Launch
// ---------------------------------------------------------------------------
extern "C" void kernel_launch(void* const* d_in, const int* in_sizes, int n_in,
                              void* d_out, int out_size)
{
    const float* x      = (const float*)d_in[0];
    const float* qkv_w  = (const float*)d_in[1];
    const float* qkv_b  = (const float*)d_in[2];
    const float* proj_w = (const float*)d_in[3];
    const float* proj_b = (const float*)d_in[4];
    const float* table  = (const float*)d_in[5];
    const int*   relidx = (const int*)d_in[6];
    float*       out    = (float*)d_out;

    __nv_bfloat16 *xb, *qkvb, *attb, *wq, *wp;
    cudaGetSymbolAddress((void**)&xb,   g_xb);
    cudaGetSymbolAddress((void**)&qkvb, g_qkv);
    cudaGetSymbolAddress((void**)&attb, g_att);
    cudaGetSymbolAddress((void**)&wq,   g_wqkv);
    cudaGetSymbolAddress((void**)&wp,   g_wprj);

    cudaFuncSetAttribute(gemm_bf16mma<true>,
        cudaFuncAttributeMaxDynamicSharedMemorySize, SMEM_GEMM);
    cudaFuncSetAttribute(gemm_bf16mma<false>,
        cudaFuncAttributeMaxDynamicSharedMemorySize, SMEM_GEMM);

    // 0) bf16 conversions
    const int nx = MTOT * DIMC / 8;
    cvt_bf16<<<(nx + 255) / 256, 256>>>(x, xb, nx);
    const int nwq = QKV_COLS * DIMC / 8;
    cvt_bf16<<<(nwq + 255) / 256, 256>>>(qkv_w, wq, nwq);
    const int nwp = DIMC * DIMC / 8;
    cvt_bf16<<<(nwp + 255) / 256, 256>>>(proj_w, wp, nwp);

    // 1) QKV GEMM -> bf16 [65536,1536]
    gemm_bf16mma<true><<<dim3(QKV_COLS / BN, MTOT / BM), 256, SMEM_GEMM>>>(
        xb, wq, qkv_b, qkvb, QKV_COLS);

    // 2) tensor-core windowed attention (window x head-pair)
    win_attn_mma<<<NWIN * (NHEADS / 2), 256>>>(qkvb, table, relidx, attb);

    // 3) projection GEMM -> f32 out
    gemm_bf16mma<false><<<dim3(DIMC / BN, MTOT / BM), 256, SMEM_GEMM>>>(
        attb, wp, proj_b, out, DIMC);
}